// round 2
// baseline (speedup 1.0000x reference)
#include <cuda_runtime.h>
#include <cuda_fp16.h>
#include <cstdint>
#include <cstddef>

using half_t = __half;

#define SEQ  8192
#define DIN  1024
#define DOUT 1024

// ---------------- device scratch (static: allowed) ----------------
__device__ half_t g_xh[SEQ * DIN];
__device__ half_t g_xl[SEQ * DIN];
__device__ half_t g_Wqh[DOUT * DIN];
__device__ half_t g_Wql[DOUT * DIN];
__device__ half_t g_Wkh[DOUT * DIN];
__device__ half_t g_Wkl[DOUT * DIN];
__device__ half_t g_Wvh[DOUT * DIN];
__device__ half_t g_Wvl[DOUT * DIN];
__device__ half_t g_Qh[SEQ * DOUT];
__device__ half_t g_Ql[SEQ * DOUT];
__device__ half_t g_Kh[SEQ * DOUT];
__device__ half_t g_Kl[SEQ * DOUT];
__device__ half_t g_Vth[(size_t)DOUT * SEQ];   // V transposed [DOUT][SEQ]
__device__ half_t g_Vtl[(size_t)DOUT * SEQ];
__device__ float  g_S [(size_t)SEQ * SEQ];     // 256 MB scores
__device__ half_t g_Ph[(size_t)SEQ * SEQ];     // probs*4096 hi
__device__ half_t g_Pl[(size_t)SEQ * SEQ];     // probs*4096 lo

// ---------------- helpers ----------------
__device__ __forceinline__ uint32_t smem_u32(const void* p) {
    uint32_t a;
    asm("{ .reg .u64 t; cvta.to.shared.u64 t, %1; cvt.u32.u64 %0, t; }" : "=r"(a) : "l"(p));
    return a;
}
__device__ __forceinline__ void cp16(uint32_t dst, const void* src) {
    asm volatile("cp.async.cg.shared.global [%0], [%1], 16;" :: "r"(dst), "l"(src));
}
#define CP_COMMIT() asm volatile("cp.async.commit_group;" ::: "memory")
#define CP_WAIT2()  asm volatile("cp.async.wait_group 2;" ::: "memory")

__device__ __forceinline__ void ldm4(uint32_t* r, uint32_t addr) {
    asm volatile("ldmatrix.sync.aligned.m8n8.x4.shared.b16 {%0,%1,%2,%3}, [%4];"
                 : "=r"(r[0]), "=r"(r[1]), "=r"(r[2]), "=r"(r[3]) : "r"(addr));
}
__device__ __forceinline__ void mma16816(float* d, const uint32_t* a, const uint32_t* b) {
    asm volatile(
        "mma.sync.aligned.m16n8k16.row.col.f32.f16.f16.f32 "
        "{%0,%1,%2,%3}, {%4,%5,%6,%7}, {%8,%9}, {%0,%1,%2,%3};"
        : "+f"(d[0]), "+f"(d[1]), "+f"(d[2]), "+f"(d[3])
        : "r"(a[0]), "r"(a[1]), "r"(a[2]), "r"(a[3]), "r"(b[0]), "r"(b[1]));
}

// ---------------- split fp32 -> (hi, lo) fp16 ----------------
__global__ void split_kernel(const float* __restrict__ src, half_t* __restrict__ hi,
                             half_t* __restrict__ lo, int n) {
    int i = blockIdx.x * blockDim.x + threadIdx.x;
    if (i < n) {
        float v = src[i];
        half_t h = __float2half_rn(v);
        hi[i] = h;
        lo[i] = __float2half_rn(v - __half2float(h));
    }
}

// ---------------- GEMM: C[MxN] = alpha * A[MxK] * B[NxK]^T via fp16x3 split ----------------
#define OUT_F32     0
#define OUT_SPLIT   1
#define OUT_SPLIT_T 2

#define KT      32              // K elements per tile
#define STRIDE  40              // smem row stride in halves (80 B, conflict-free)
#define TILE_H  (128 * STRIDE)  // 5120 halves per operand tile
#define STAGE_H (4 * TILE_H)    // 20480 halves per stage
#define STAGE_B (STAGE_H * 2)   // 40960 bytes
#define STAGES  4
#define GEMM_SMEM_BYTES (STAGES * STAGE_B)   // 163840

template <int MODE>
__global__ __launch_bounds__(256, 1)
void gemm_nt_kernel(const half_t* __restrict__ Ah, const half_t* __restrict__ Al,
                    const half_t* __restrict__ Bh, const half_t* __restrict__ Bl,
                    float* __restrict__ outF, half_t* __restrict__ outH, half_t* __restrict__ outL,
                    int K, int ldc, float alpha) {
    extern __shared__ half_t sm[];
    const uint32_t sbase = smem_u32(sm);
    const int tid  = threadIdx.x;
    const int lane = tid & 31;
    const int wid  = tid >> 5;
    const int m0 = blockIdx.y * 128;
    const int n0 = blockIdx.x * 128;
    const int wm = (wid & 1) * 64;         // warp M offset within CTA tile
    const int wn = (wid >> 1) * 32;        // warp N offset

    // --- per-thread cp.async source/dst precompute (8 x 16B chunks per stage) ---
    const half_t* src0[8];
    uint32_t      soff[8];
    const half_t* bases[4] = {Ah, Al, Bh, Bl};
#pragma unroll
    for (int i = 0; i < 8; i++) {
        int c = tid + i * 256;             // 0..2047
        int t = c >> 9;                    // tile 0..3
        int r = (c & 511) >> 2;            // row 0..127
        int j = c & 3;                     // 16B chunk within 64B row
        int grow = (t < 2 ? m0 : n0) + r;
        src0[i] = bases[t] + (size_t)grow * K + j * 8;
        soff[i] = (uint32_t)((t * TILE_H + r * STRIDE + j * 8) * 2);
    }

    auto load_stage = [&](int s, int kt) {
        uint32_t dstb = sbase + s * STAGE_B;
#pragma unroll
        for (int i = 0; i < 8; i++)
            cp16(dstb + soff[i], src0[i] + kt * KT);
    };

    float acc[4][4][4];
#pragma unroll
    for (int mt = 0; mt < 4; mt++)
#pragma unroll
        for (int nt = 0; nt < 4; nt++)
#pragma unroll
            for (int e = 0; e < 4; e++) acc[mt][nt][e] = 0.0f;

    const int nkt = K / KT;
    // prologue: fill STAGES-1 stages
#pragma unroll
    for (int s = 0; s < STAGES - 1; s++) {
        load_stage(s, s);
        CP_COMMIT();
    }

    // ldmatrix address components (stage-invariant parts)
    const int arow = wm + (lane & 15);
    const int acolsel = ((lane >> 4) & 1) * 8;
    const int brow = wn + ((lane >> 4) & 1) * 8 + (lane & 7);
    const int bcolsel = ((lane >> 3) & 1) * 8;

#pragma unroll 1
    for (int kt = 0; kt < nkt; kt++) {
        CP_WAIT2();
        __syncthreads();
        const int s = kt & (STAGES - 1);
        if (kt + STAGES - 1 < nkt) load_stage((kt + STAGES - 1) & (STAGES - 1), kt + STAGES - 1);
        CP_COMMIT();

        const uint32_t stb = sbase + s * STAGE_B;
#pragma unroll
        for (int kk = 0; kk < 2; kk++) {    // two k16 steps
            const int kc = kk * 16;
            uint32_t a_h[4][4], a_l[4][4], b_h[4][2], b_l[4][2];
#pragma unroll
            for (int mt = 0; mt < 4; mt++) {
                uint32_t off = (uint32_t)(((arow + mt * 16) * STRIDE + kc + acolsel) * 2);
                ldm4(a_h[mt], stb + off);                    // Ah tile
                ldm4(a_l[mt], stb + TILE_H * 2 + off);       // Al tile
            }
#pragma unroll
            for (int pt = 0; pt < 2; pt++) {
                uint32_t off = (uint32_t)(((brow + pt * 16) * STRIDE + kc + bcolsel) * 2);
                uint32_t r[4];
                ldm4(r, stb + TILE_H * 4 + off);             // Bh tile
                b_h[2 * pt][0] = r[0]; b_h[2 * pt][1] = r[1];
                b_h[2 * pt + 1][0] = r[2]; b_h[2 * pt + 1][1] = r[3];
                ldm4(r, stb + TILE_H * 6 + off);             // Bl tile
                b_l[2 * pt][0] = r[0]; b_l[2 * pt][1] = r[1];
                b_l[2 * pt + 1][0] = r[2]; b_l[2 * pt + 1][1] = r[3];
            }
#pragma unroll
            for (int mt = 0; mt < 4; mt++)
#pragma unroll
                for (int nt = 0; nt < 4; nt++) {
                    mma16816(acc[mt][nt], a_h[mt], b_h[nt]);   // hi*hi
                    mma16816(acc[mt][nt], a_h[mt], b_l[nt]);   // hi*lo
                    mma16816(acc[mt][nt], a_l[mt], b_h[nt]);   // lo*hi
                }
        }
    }

    // ---------------- epilogue (register-direct) ----------------
    const int rr = lane >> 2;              // 0..7
    const int cc = (lane & 3) * 2;         // 0,2,4,6
#pragma unroll
    for (int mt = 0; mt < 4; mt++) {
#pragma unroll
        for (int nt = 0; nt < 4; nt++) {
            int gm = m0 + wm + mt * 16 + rr;
            int gn = n0 + wn + nt * 8 + cc;
#pragma unroll
            for (int h = 0; h < 2; h++) {   // row, row+8
                float v0 = acc[mt][nt][2 * h + 0] * alpha;
                float v1 = acc[mt][nt][2 * h + 1] * alpha;
                int m = gm + h * 8;
                if (MODE == OUT_F32) {
                    float2 v; v.x = v0; v.y = v1;
                    *(float2*)(outF + (size_t)m * ldc + gn) = v;
                } else if (MODE == OUT_SPLIT) {
                    half_t h0 = __float2half_rn(v0), h1 = __float2half_rn(v1);
                    half_t l0 = __float2half_rn(v0 - __half2float(h0));
                    half_t l1 = __float2half_rn(v1 - __half2float(h1));
                    *(__half2*)(outH + (size_t)m * ldc + gn) = __halves2half2(h0, h1);
                    *(__half2*)(outL + (size_t)m * ldc + gn) = __halves2half2(l0, l1);
                } else {  // OUT_SPLIT_T: out[(n)*ldc + m]
                    half_t h0 = __float2half_rn(v0), h1 = __float2half_rn(v1);
                    half_t l0 = __float2half_rn(v0 - __half2float(h0));
                    half_t l1 = __float2half_rn(v1 - __half2float(h1));
                    outH[(size_t)gn * ldc + m] = h0;
                    outH[(size_t)(gn + 1) * ldc + m] = h1;
                    outL[(size_t)gn * ldc + m] = l0;
                    outL[(size_t)(gn + 1) * ldc + m] = l1;
                }
            }
        }
    }
}

// ---------------- softmax over rows of S, write split probs * 4096 ----------------
__global__ __launch_bounds__(256)
void softmax_kernel(const float* __restrict__ S, half_t* __restrict__ Ph, half_t* __restrict__ Pl) {
    __shared__ float buf[SEQ];
    __shared__ float red[8];
    const int row = blockIdx.x;
    const int tid = threadIdx.x;
    const float* s = S + (size_t)row * SEQ;

    float mx = -1e30f;
    for (int i = tid; i < SEQ; i += 256) {
        float v = s[i];
        buf[i] = v;
        mx = fmaxf(mx, v);
    }
#pragma unroll
    for (int o = 16; o; o >>= 1) mx = fmaxf(mx, __shfl_xor_sync(0xFFFFFFFFu, mx, o));
    if ((tid & 31) == 0) red[tid >> 5] = mx;
    __syncthreads();
    mx = red[0];
#pragma unroll
    for (int j = 1; j < 8; j++) mx = fmaxf(mx, red[j]);
    __syncthreads();

    float sum = 0.0f;
    for (int i = tid; i < SEQ; i += 256) {
        float e = __expf(buf[i] - mx);
        buf[i] = e;
        sum += e;
    }
#pragma unroll
    for (int o = 16; o; o >>= 1) sum += __shfl_xor_sync(0xFFFFFFFFu, sum, o);
    if ((tid & 31) == 0) red[tid >> 5] = sum;
    __syncthreads();
    sum = 0.0f;
#pragma unroll
    for (int j = 0; j < 8; j++) sum += red[j];
    const float inv = 4096.0f / sum;   // scale by 4096 keeps lo-half out of fp16 subnormals

    half_t* ph = Ph + (size_t)row * SEQ;
    half_t* pl = Pl + (size_t)row * SEQ;
    for (int i = tid; i < SEQ; i += 256) {
        float pv = buf[i] * inv;
        half_t h = __float2half_rn(pv);
        ph[i] = h;
        pl[i] = __float2half_rn(pv - __half2float(h));
    }
}

// ---------------- host ----------------
extern "C" void kernel_launch(void* const* d_in, const int* in_sizes, int n_in,
                              void* d_out, int out_size) {
    const float* x  = (const float*)d_in[0];
    const float* Wq = (const float*)d_in[1];
    const float* Wk = (const float*)d_in[2];
    const float* Wv = (const float*)d_in[3];
    float* out = (float*)d_out;

    half_t *xh, *xl, *wqh, *wql, *wkh, *wkl, *wvh, *wvl;
    half_t *qh, *ql, *kh, *kl, *vth, *vtl, *pph, *ppl;
    float* sp;
    cudaGetSymbolAddress((void**)&xh,  g_xh);
    cudaGetSymbolAddress((void**)&xl,  g_xl);
    cudaGetSymbolAddress((void**)&wqh, g_Wqh);
    cudaGetSymbolAddress((void**)&wql, g_Wql);
    cudaGetSymbolAddress((void**)&wkh, g_Wkh);
    cudaGetSymbolAddress((void**)&wkl, g_Wkl);
    cudaGetSymbolAddress((void**)&wvh, g_Wvh);
    cudaGetSymbolAddress((void**)&wvl, g_Wvl);
    cudaGetSymbolAddress((void**)&qh,  g_Qh);
    cudaGetSymbolAddress((void**)&ql,  g_Ql);
    cudaGetSymbolAddress((void**)&kh,  g_Kh);
    cudaGetSymbolAddress((void**)&kl,  g_Kl);
    cudaGetSymbolAddress((void**)&vth, g_Vth);
    cudaGetSymbolAddress((void**)&vtl, g_Vtl);
    cudaGetSymbolAddress((void**)&pph, g_Ph);
    cudaGetSymbolAddress((void**)&ppl, g_Pl);
    cudaGetSymbolAddress((void**)&sp,  g_S);

    cudaFuncSetAttribute(gemm_nt_kernel<OUT_F32>,     cudaFuncAttributeMaxDynamicSharedMemorySize, GEMM_SMEM_BYTES);
    cudaFuncSetAttribute(gemm_nt_kernel<OUT_SPLIT>,   cudaFuncAttributeMaxDynamicSharedMemorySize, GEMM_SMEM_BYTES);
    cudaFuncSetAttribute(gemm_nt_kernel<OUT_SPLIT_T>, cudaFuncAttributeMaxDynamicSharedMemorySize, GEMM_SMEM_BYTES);

    // 1) split fp32 inputs into hi/lo fp16
    split_kernel<<<(SEQ * DIN + 255) / 256, 256>>>(x, xh, xl, SEQ * DIN);
    split_kernel<<<(DOUT * DIN + 255) / 256, 256>>>(Wq, wqh, wql, DOUT * DIN);
    split_kernel<<<(DOUT * DIN + 255) / 256, 256>>>(Wk, wkh, wkl, DOUT * DIN);
    split_kernel<<<(DOUT * DIN + 255) / 256, 256>>>(Wv, wvh, wvl, DOUT * DIN);

    // 2) projections: Q = x Wq^T, K = x Wk^T (split), V^T (split, transposed store)
    dim3 gproj(DOUT / 128, SEQ / 128);
    gemm_nt_kernel<OUT_SPLIT><<<gproj, 256, GEMM_SMEM_BYTES>>>(xh, xl, wqh, wql, nullptr, qh, ql, DIN, DOUT, 1.0f);
    gemm_nt_kernel<OUT_SPLIT><<<gproj, 256, GEMM_SMEM_BYTES>>>(xh, xl, wkh, wkl, nullptr, kh, kl, DIN, DOUT, 1.0f);
    gemm_nt_kernel<OUT_SPLIT_T><<<gproj, 256, GEMM_SMEM_BYTES>>>(xh, xl, wvh, wvl, nullptr, vth, vtl, DIN, SEQ, 1.0f);

    // 3) scores: S = (Q K^T) / 32
    dim3 gsc(SEQ / 128, SEQ / 128);
    gemm_nt_kernel<OUT_F32><<<gsc, 256, GEMM_SMEM_BYTES>>>(qh, ql, kh, kl, sp, nullptr, nullptr, DIN, SEQ, 0.03125f);

    // 4) softmax rows -> split probs (scaled by 4096)
    softmax_kernel<<<SEQ, 256>>>(sp, pph, ppl);

    // 5) O = (P*4096) @ V / 4096  (NT against V^T)
    dim3 gout(DOUT / 128, SEQ / 128);
    gemm_nt_kernel<OUT_F32><<<gout, 256, GEMM_SMEM_BYTES>>>(pph, ppl, vth, vtl, out, nullptr, nullptr, SEQ, DOUT, 1.0f / 4096.0f);
}

// round 3
// speedup vs baseline: 1.1745x; 1.1745x over previous
#include <cuda_runtime.h>
#include <cuda_fp16.h>
#include <cstdint>
#include <cstddef>

using half_t = __half;

#define SEQ  8192
#define DIN  1024
#define DOUT 1024

// ---------------- device scratch (static: allowed) ----------------
__device__ half_t g_xh[SEQ * DIN];
__device__ half_t g_xl[SEQ * DIN];
__device__ half_t g_Wqh[DOUT * DIN];
__device__ half_t g_Wql[DOUT * DIN];
__device__ half_t g_Wkh[DOUT * DIN];
__device__ half_t g_Wkl[DOUT * DIN];
__device__ half_t g_Wvh[DOUT * DIN];
__device__ half_t g_Wvl[DOUT * DIN];
__device__ half_t g_Qh[SEQ * DOUT];
__device__ half_t g_Ql[SEQ * DOUT];
__device__ half_t g_Kh[SEQ * DOUT];
__device__ half_t g_Kl[SEQ * DOUT];
__device__ half_t g_Vth[(size_t)DOUT * SEQ];   // V transposed [DOUT][SEQ]
__device__ half_t g_Vtl[(size_t)DOUT * SEQ];
__device__ float  g_S [(size_t)SEQ * SEQ];     // 256 MB scores
__device__ half_t g_Ph[(size_t)SEQ * SEQ];     // probs*4096 (hi only; 2-term PV)

// ---------------- helpers ----------------
__device__ __forceinline__ uint32_t smem_u32(const void* p) {
    uint32_t a;
    asm("{ .reg .u64 t; cvta.to.shared.u64 t, %1; cvt.u32.u64 %0, t; }" : "=r"(a) : "l"(p));
    return a;
}
__device__ __forceinline__ void cp16(uint32_t dst, const void* src) {
    asm volatile("cp.async.cg.shared.global [%0], [%1], 16;" :: "r"(dst), "l"(src));
}
#define CP_COMMIT() asm volatile("cp.async.commit_group;" ::: "memory")
#define CP_WAIT2()  asm volatile("cp.async.wait_group 2;" ::: "memory")

__device__ __forceinline__ void ldm4(uint32_t* r, uint32_t addr) {
    asm volatile("ldmatrix.sync.aligned.m8n8.x4.shared.b16 {%0,%1,%2,%3}, [%4];"
                 : "=r"(r[0]), "=r"(r[1]), "=r"(r[2]), "=r"(r[3]) : "r"(addr));
}
__device__ __forceinline__ void mma16816(float* d, const uint32_t* a, const uint32_t* b) {
    asm volatile(
        "mma.sync.aligned.m16n8k16.row.col.f32.f16.f16.f32 "
        "{%0,%1,%2,%3}, {%4,%5,%6,%7}, {%8,%9}, {%0,%1,%2,%3};"
        : "+f"(d[0]), "+f"(d[1]), "+f"(d[2]), "+f"(d[3])
        : "r"(a[0]), "r"(a[1]), "r"(a[2]), "r"(a[3]), "r"(b[0]), "r"(b[1]));
}

// ---------------- split fp32 -> (hi, lo) fp16 ----------------
__global__ void split_kernel(const float* __restrict__ src, half_t* __restrict__ hi,
                             half_t* __restrict__ lo, int n) {
    int i = blockIdx.x * blockDim.x + threadIdx.x;
    if (i < n) {
        float v = src[i];
        half_t h = __float2half_rn(v);
        hi[i] = h;
        lo[i] = __float2half_rn(v - __half2float(h));
    }
}

// ---------------- GEMM: C[MxN] = alpha * A[MxK] * B[NxK]^T via fp16 split ----------------
// ALO=true : 3-term (Ah*Bh + Ah*Bl + Al*Bh)  — smem tiles [Ah, Bh, Bl, Al]
// ALO=false: 2-term (Ah*Bh + Ah*Bl)          — smem tiles [Ah, Bh, Bl]
#define OUT_F32     0
#define OUT_SPLIT   1
#define OUT_SPLIT_T 2

#define KT      32              // K elements per tile
#define STRIDE  40              // smem row stride in halves (80 B, conflict-free)
#define TILE_H  (128 * STRIDE)  // 5120 halves per operand tile
#define TILE_B  (TILE_H * 2)    // 10240 bytes
#define STAGES  4
#define SMEM_ALO   (STAGES * 4 * TILE_B)   // 163840
#define SMEM_NOALO (STAGES * 3 * TILE_B)   // 122880

template <int MODE, bool ALO>
__global__ __launch_bounds__(256, 1)
void gemm_nt_kernel(const half_t* __restrict__ Ah, const half_t* __restrict__ Al,
                    const half_t* __restrict__ Bh, const half_t* __restrict__ Bl,
                    float* __restrict__ outF, half_t* __restrict__ outH, half_t* __restrict__ outL,
                    int K, int ldc, float alpha) {
    constexpr int NTILES  = ALO ? 4 : 3;
    constexpr int STAGE_B = NTILES * TILE_B;

    extern __shared__ half_t sm[];
    const uint32_t sbase = smem_u32(sm);
    const int tid  = threadIdx.x;
    const int lane = tid & 31;
    const int wid  = tid >> 5;
    const int m0 = blockIdx.y * 128;
    const int n0 = blockIdx.x * 128;
    const int wm = (wid & 1) * 64;         // warp M offset
    const int wn = (wid >> 1) * 32;        // warp N offset

    // --- cp.async source/dst precompute: tiles order [Ah, Bh, Bl, (Al)] ---
    const half_t* src0[2 * NTILES];
    uint32_t      soff[2 * NTILES];
    {
        const half_t* bases[4] = {Ah, Bh, Bl, Al};
#pragma unroll
        for (int i = 0; i < 2 * NTILES; i++) {
            int c = tid + i * 256;             // 0 .. 512*NTILES-1
            int t = c >> 9;                    // tile idx
            int r = (c & 511) >> 2;            // row 0..127
            int j = c & 3;                     // 16B chunk
            int grow = ((t == 0 || t == 3) ? m0 : n0) + r;
            src0[i] = bases[t] + (size_t)grow * K + j * 8;
            soff[i] = (uint32_t)(t * TILE_B + (r * STRIDE + j * 8) * 2);
        }
    }
    auto load_stage = [&](int s, int kt) {
        uint32_t dstb = sbase + s * STAGE_B;
#pragma unroll
        for (int i = 0; i < 2 * NTILES; i++)
            cp16(dstb + soff[i], src0[i] + kt * KT);
    };

    float acc[4][4][4];
#pragma unroll
    for (int mt = 0; mt < 4; mt++)
#pragma unroll
        for (int nt = 0; nt < 4; nt++)
#pragma unroll
            for (int e = 0; e < 4; e++) acc[mt][nt][e] = 0.0f;

    // ldmatrix address components
    const int arow    = wm + (lane & 15);
    const int acolsel = ((lane >> 4) & 1) * 8;
    const int brow    = wn + ((lane >> 4) & 1) * 8 + (lane & 7);
    const int bcolsel = ((lane >> 3) & 1) * 8;

    // fragment double buffers (2 kk-steps in flight)
    uint32_t a_h[2][4][4], a_l[2][4][4], b_h[2][4][2], b_l[2][4][2];

    auto load_frags = [&](int buf, uint32_t stb, int kc) {
#pragma unroll
        for (int mt = 0; mt < 4; mt++) {
            uint32_t off = (uint32_t)(((arow + mt * 16) * STRIDE + kc + acolsel) * 2);
            ldm4(a_h[buf][mt], stb + off);
            if (ALO) ldm4(a_l[buf][mt], stb + 3 * TILE_B + off);
        }
#pragma unroll
        for (int pt = 0; pt < 2; pt++) {
            uint32_t off = (uint32_t)(((brow + pt * 16) * STRIDE + kc + bcolsel) * 2);
            uint32_t r[4];
            ldm4(r, stb + TILE_B + off);                 // Bh
            b_h[buf][2 * pt][0] = r[0]; b_h[buf][2 * pt][1] = r[1];
            b_h[buf][2 * pt + 1][0] = r[2]; b_h[buf][2 * pt + 1][1] = r[3];
            ldm4(r, stb + 2 * TILE_B + off);             // Bl
            b_l[buf][2 * pt][0] = r[0]; b_l[buf][2 * pt][1] = r[1];
            b_l[buf][2 * pt + 1][0] = r[2]; b_l[buf][2 * pt + 1][1] = r[3];
        }
    };
    auto do_mmas = [&](int buf) {
#pragma unroll
        for (int mt = 0; mt < 4; mt++)
#pragma unroll
            for (int nt = 0; nt < 4; nt++) {
                mma16816(acc[mt][nt], a_h[buf][mt], b_h[buf][nt]);   // hi*hi
                mma16816(acc[mt][nt], a_h[buf][mt], b_l[buf][nt]);   // hi*lo
                if (ALO) mma16816(acc[mt][nt], a_l[buf][mt], b_h[buf][nt]);  // lo*hi
            }
    };

    const int nkt = K / KT;
    // prologue: stages 0..2
#pragma unroll
    for (int s = 0; s < STAGES - 1; s++) {
        load_stage(s, s);
        CP_COMMIT();
    }
    CP_WAIT2();
    __syncthreads();
    load_frags(0, sbase, 0);

#pragma unroll 1
    for (int kt = 0; kt < nkt; kt++) {
        const uint32_t stb = sbase + (kt & (STAGES - 1)) * STAGE_B;
        if (kt + STAGES - 1 < nkt) load_stage((kt + STAGES - 1) & (STAGES - 1), kt + STAGES - 1);
        CP_COMMIT();
        load_frags(1, stb, 16);      // kk=1 frags in flight over kk=0 MMAs
        do_mmas(0);
        if (kt + 1 < nkt) {
            CP_WAIT2();
            __syncthreads();
            load_frags(0, sbase + ((kt + 1) & (STAGES - 1)) * STAGE_B, 0);  // next iter kk=0
        }
        do_mmas(1);                  // overlaps next-iter frag loads
    }

    // ---------------- epilogue (register-direct) ----------------
    const int rr = lane >> 2;
    const int cc = (lane & 3) * 2;
#pragma unroll
    for (int mt = 0; mt < 4; mt++) {
#pragma unroll
        for (int nt = 0; nt < 4; nt++) {
            int gm = m0 + wm + mt * 16 + rr;
            int gn = n0 + wn + nt * 8 + cc;
#pragma unroll
            for (int h = 0; h < 2; h++) {
                float v0 = acc[mt][nt][2 * h + 0] * alpha;
                float v1 = acc[mt][nt][2 * h + 1] * alpha;
                int m = gm + h * 8;
                if (MODE == OUT_F32) {
                    float2 v; v.x = v0; v.y = v1;
                    *(float2*)(outF + (size_t)m * ldc + gn) = v;
                } else if (MODE == OUT_SPLIT) {
                    half_t h0 = __float2half_rn(v0), h1 = __float2half_rn(v1);
                    half_t l0 = __float2half_rn(v0 - __half2float(h0));
                    half_t l1 = __float2half_rn(v1 - __half2float(h1));
                    *(__half2*)(outH + (size_t)m * ldc + gn) = __halves2half2(h0, h1);
                    *(__half2*)(outL + (size_t)m * ldc + gn) = __halves2half2(l0, l1);
                } else {  // OUT_SPLIT_T
                    half_t h0 = __float2half_rn(v0), h1 = __float2half_rn(v1);
                    half_t l0 = __float2half_rn(v0 - __half2float(h0));
                    half_t l1 = __float2half_rn(v1 - __half2float(h1));
                    outH[(size_t)gn * ldc + m] = h0;
                    outH[(size_t)(gn + 1) * ldc + m] = h1;
                    outL[(size_t)gn * ldc + m] = l0;
                    outL[(size_t)(gn + 1) * ldc + m] = l1;
                }
            }
        }
    }
}

// ---------------- softmax over rows of S, write probs * 4096 (hi only) ----------------
__global__ __launch_bounds__(256)
void softmax_kernel(const float* __restrict__ S, half_t* __restrict__ Ph) {
    __shared__ float buf[SEQ];
    __shared__ float red[8];
    const int row = blockIdx.x;
    const int tid = threadIdx.x;
    const float* s = S + (size_t)row * SEQ;

    float mx = -1e30f;
    for (int i = tid; i < SEQ; i += 256) {
        float v = s[i];
        buf[i] = v;
        mx = fmaxf(mx, v);
    }
#pragma unroll
    for (int o = 16; o; o >>= 1) mx = fmaxf(mx, __shfl_xor_sync(0xFFFFFFFFu, mx, o));
    if ((tid & 31) == 0) red[tid >> 5] = mx;
    __syncthreads();
    mx = red[0];
#pragma unroll
    for (int j = 1; j < 8; j++) mx = fmaxf(mx, red[j]);
    __syncthreads();

    float sum = 0.0f;
    for (int i = tid; i < SEQ; i += 256) {
        float e = __expf(buf[i] - mx);
        buf[i] = e;
        sum += e;
    }
#pragma unroll
    for (int o = 16; o; o >>= 1) sum += __shfl_xor_sync(0xFFFFFFFFu, sum, o);
    if ((tid & 31) == 0) red[tid >> 5] = sum;
    __syncthreads();
    sum = 0.0f;
#pragma unroll
    for (int j = 0; j < 8; j++) sum += red[j];
    const float inv = 4096.0f / sum;

    half_t* ph = Ph + (size_t)row * SEQ;
    for (int i = tid; i < SEQ; i += 256)
        ph[i] = __float2half_rn(buf[i] * inv);
}

// ---------------- host ----------------
extern "C" void kernel_launch(void* const* d_in, const int* in_sizes, int n_in,
                              void* d_out, int out_size) {
    const float* x  = (const float*)d_in[0];
    const float* Wq = (const float*)d_in[1];
    const float* Wk = (const float*)d_in[2];
    const float* Wv = (const float*)d_in[3];
    float* out = (float*)d_out;

    half_t *xh, *xl, *wqh, *wql, *wkh, *wkl, *wvh, *wvl;
    half_t *qh, *ql, *kh, *kl, *vth, *vtl, *pph;
    float* sp;
    cudaGetSymbolAddress((void**)&xh,  g_xh);
    cudaGetSymbolAddress((void**)&xl,  g_xl);
    cudaGetSymbolAddress((void**)&wqh, g_Wqh);
    cudaGetSymbolAddress((void**)&wql, g_Wql);
    cudaGetSymbolAddress((void**)&wkh, g_Wkh);
    cudaGetSymbolAddress((void**)&wkl, g_Wkl);
    cudaGetSymbolAddress((void**)&wvh, g_Wvh);
    cudaGetSymbolAddress((void**)&wvl, g_Wvl);
    cudaGetSymbolAddress((void**)&qh,  g_Qh);
    cudaGetSymbolAddress((void**)&ql,  g_Ql);
    cudaGetSymbolAddress((void**)&kh,  g_Kh);
    cudaGetSymbolAddress((void**)&kl,  g_Kl);
    cudaGetSymbolAddress((void**)&vth, g_Vth);
    cudaGetSymbolAddress((void**)&vtl, g_Vtl);
    cudaGetSymbolAddress((void**)&pph, g_Ph);
    cudaGetSymbolAddress((void**)&sp,  g_S);

    cudaFuncSetAttribute((const void*)gemm_nt_kernel<OUT_SPLIT,   true>,
                         cudaFuncAttributeMaxDynamicSharedMemorySize, SMEM_ALO);
    cudaFuncSetAttribute((const void*)gemm_nt_kernel<OUT_SPLIT_T, true>,
                         cudaFuncAttributeMaxDynamicSharedMemorySize, SMEM_ALO);
    cudaFuncSetAttribute((const void*)gemm_nt_kernel<OUT_F32,     true>,
                         cudaFuncAttributeMaxDynamicSharedMemorySize, SMEM_ALO);
    cudaFuncSetAttribute((const void*)gemm_nt_kernel<OUT_F32,     false>,
                         cudaFuncAttributeMaxDynamicSharedMemorySize, SMEM_NOALO);

    // 1) split fp32 inputs into hi/lo fp16
    split_kernel<<<(SEQ * DIN + 255) / 256, 256>>>(x, xh, xl, SEQ * DIN);
    split_kernel<<<(DOUT * DIN + 255) / 256, 256>>>(Wq, wqh, wql, DOUT * DIN);
    split_kernel<<<(DOUT * DIN + 255) / 256, 256>>>(Wk, wkh, wkl, DOUT * DIN);
    split_kernel<<<(DOUT * DIN + 255) / 256, 256>>>(Wv, wvh, wvl, DOUT * DIN);

    // 2) projections (3-term): Q, K split; V^T split transposed
    dim3 gproj(DOUT / 128, SEQ / 128);
    gemm_nt_kernel<OUT_SPLIT,   true><<<gproj, 256, SMEM_ALO>>>(xh, xl, wqh, wql, nullptr, qh, ql, DIN, DOUT, 1.0f);
    gemm_nt_kernel<OUT_SPLIT,   true><<<gproj, 256, SMEM_ALO>>>(xh, xl, wkh, wkl, nullptr, kh, kl, DIN, DOUT, 1.0f);
    gemm_nt_kernel<OUT_SPLIT_T, true><<<gproj, 256, SMEM_ALO>>>(xh, xl, wvh, wvl, nullptr, vth, vtl, DIN, SEQ, 1.0f);

    // 3) scores (3-term): S = (Q K^T) / 32
    dim3 gsc(SEQ / 128, SEQ / 128);
    gemm_nt_kernel<OUT_F32, true><<<gsc, 256, SMEM_ALO>>>(qh, ql, kh, kl, sp, nullptr, nullptr, DIN, SEQ, 0.03125f);

    // 4) softmax rows -> probs*4096 (hi only)
    softmax_kernel<<<SEQ, 256>>>(sp, pph);

    // 5) O = (P*4096) @ V / 4096, 2-term (Ph*Vh + Ph*Vl)
    dim3 gout(DOUT / 128, SEQ / 128);
    gemm_nt_kernel<OUT_F32, false><<<gout, 256, SMEM_NOALO>>>(pph, nullptr, vth, vtl, out, nullptr, nullptr, SEQ, DOUT, 1.0f / 4096.0f);
}